// round 7
// baseline (speedup 1.0000x reference)
#include <cuda_runtime.h>

// Problem constants
#define H_ 128
#define W_ 128
#define C_ 32
#define NPIX_ (8 * 11 * 128 * 128)   // 1,441,792 pixels
#define PPB_ 256                     // pixels per block
#define NBLOCKS_ (NPIX_ / PPB_)      // 5632

// Per-pixel packed params (16 B):
//   .x = byte offset of 2x2 footprint base (always fully in-bounds)
//   .y = w00 | (w01 << 16)   (u16 fixed-point, x65535)
//   .z = w10 | (w11 << 16)
//   .w = unused
__global__ void __launch_bounds__(256, 1) deform_kernel(
    const float* __restrict__ src,   // (H, W, C) = (128,128,32)
    const float* __restrict__ mot,   // (NPIX, 2)
    float* __restrict__ out)         // (NPIX, C)
{
    __shared__ int4 s_p[PPB_];

    const int t = threadIdx.x;
    const int blockPix = blockIdx.x * PPB_;

    // ---- Phase 1: each thread computes params for one pixel ----
    {
        const int pix = blockPix + t;
        float2 g = __ldg(((const float2*)mot) + pix);
        float gx = fmaf(g.x, 64.0f, 63.5f);   // (g+1)*64 - 0.5
        float gy = fmaf(g.y, 64.0f, 63.5f);

        float xf = floorf(gx);
        float yf = floorf(gy);
        float fx = gx - xf;      // 'w'
        float fy = gy - yf;      // 'n'
        float ex = 1.0f - fx;    // 'e'
        float sy = 1.0f - fy;    // 's'

        int x0 = (int)xf;
        int y0 = (int)yf;

        bool mx0 = (unsigned)x0 < 128u;
        bool mx1 = (unsigned)(x0 + 1) < 128u;
        bool my0 = (unsigned)y0 < 128u;
        bool my1 = (unsigned)(y0 + 1) < 128u;

        // base clamped so the whole 2x2 footprint is in-bounds
        int bx = min(max(x0, 0), 126);
        int by = min(max(y0, 0), 126);

        // x-axis weights mapped onto span [bx, bx+1]
        //  normal: (ex, fx); x0 oob-left: x1 data sits at lo -> (fx, 0);
        //  x1 oob-right: x0 data sits at hi -> (0, ex); both oob: (0,0)
        float ax_lo, ax_hi;
        if (mx0 & mx1)      { ax_lo = ex;   ax_hi = fx;   }
        else if (mx1)       { ax_lo = fx;   ax_hi = 0.0f; }
        else if (mx0)       { ax_lo = 0.0f; ax_hi = ex;   }
        else                { ax_lo = 0.0f; ax_hi = 0.0f; }

        float ay_lo, ay_hi;
        if (my0 & my1)      { ay_lo = sy;   ay_hi = fy;   }
        else if (my1)       { ay_lo = fy;   ay_hi = 0.0f; }
        else if (my0)       { ay_lo = 0.0f; ay_hi = sy;   }
        else                { ay_lo = 0.0f; ay_hi = 0.0f; }

        unsigned q00 = __float2uint_rn(ay_lo * ax_lo * 65535.0f);
        unsigned q01 = __float2uint_rn(ay_lo * ax_hi * 65535.0f);
        unsigned q10 = __float2uint_rn(ay_hi * ax_lo * 65535.0f);
        unsigned q11 = __float2uint_rn(ay_hi * ax_hi * 65535.0f);

        int4 prm;
        prm.x = ((by << 7) + bx) << 7;         // byte offset of (by,bx,c=0)
        prm.y = (int)(q00 | (q01 << 16));
        prm.z = (int)(q10 | (q11 << 16));
        prm.w = 0;
        s_p[t] = prm;
    }
    __syncthreads();

    // ---- Phase 2: 2 pixels per warp-iteration.
    //      lanes 0-15 -> pixel A (channels 2m,2m+1), lanes 16-31 -> pixel B.
    const int lane = t & 31;
    const int warp = t >> 5;
    const int half = lane >> 4;      // which pixel of the pair
    const int m    = lane & 15;      // channel pair index

    const char* __restrict__ srcB = (const char*)src + (m << 3);  // +8m bytes
    const int4* __restrict__ pp = s_p + (warp << 5) + half;        // stride 2 pixels
    char* __restrict__ outB = (char*)out
        + (((blockPix + (warp << 5) + half)) << 7) + (m << 3);

    #pragma unroll
    for (int it = 0; it < 16; ++it) {
        int4 prm = pp[it << 1];                 // LDS.128, imm offset

        const float2* a = (const float2*)(srcB + prm.x);
        float2 v00 = __ldg(a);                  // base + 0
        float2 v01 = __ldg(a + 16);             // base + 128 B   (x+1)
        float2 v10 = __ldg(a + 2048);           // base + 16384 B (y+1)
        float2 v11 = __ldg(a + 2064);           // base + 16512 B (y+1,x+1)

        unsigned pa = (unsigned)prm.y;
        unsigned pb = (unsigned)prm.z;
        float w00 = (float)(pa & 0xFFFFu);
        float w01 = (float)(pa >> 16);
        float w10 = (float)(pb & 0xFFFFu);
        float w11 = (float)(pb >> 16);

        float rx = fmaf(w00, v00.x, fmaf(w01, v01.x, fmaf(w10, v10.x, w11 * v11.x)));
        float ry = fmaf(w00, v00.y, fmaf(w01, v01.y, fmaf(w10, v10.y, w11 * v11.y)));

        float2 o2;
        o2.x = rx * (1.0f / 65535.0f);
        o2.y = ry * (1.0f / 65535.0f);
        *(float2*)(outB + (it << 8)) = o2;      // STG.64, imm offset (2 px = 256 B)
    }
}

extern "C" void kernel_launch(void* const* d_in, const int* in_sizes, int n_in,
                              void* d_out, int out_size)
{
    const float* src = (const float*)d_in[0];   // source (1,H,W,C)
    const float* mot = (const float*)d_in[1];   // motions (BS,NKP,H,W,2)
    float* out = (float*)d_out;

    deform_kernel<<<NBLOCKS_, 256>>>(src, mot, out);
}

// round 10
// speedup vs baseline: 2.0012x; 2.0012x over previous
#include <cuda_runtime.h>

// Problem constants
#define H_ 128
#define W_ 128
#define C_ 32
#define NPIX_ (8 * 11 * 128 * 128)   // 1,441,792 pixels
#define PPB_ 256                     // pixels per block
#define NBLOCKS_ (NPIX_ / PPB_)      // 5632

// Per-pixel packed params (16 B):
//   .x = byte offset of 2x2 footprint base (always fully in-bounds)
//   .y = w00 | (w01 << 16)   (u16 fixed-point, x65535)
//   .z = w10 | (w11 << 16)
//   .w = unused
__global__ void __launch_bounds__(256, 4) deform_kernel(
    const float* __restrict__ src,   // (H, W, C) = (128,128,32)
    const float* __restrict__ mot,   // (NPIX, 2)
    float* __restrict__ out)         // (NPIX, C)
{
    __shared__ int4 s_p[PPB_];

    const int t = threadIdx.x;
    const int blockPix = blockIdx.x * PPB_;

    // ---- Phase 1: each thread computes params for one pixel ----
    {
        const int pix = blockPix + t;
        float2 g = __ldg(((const float2*)mot) + pix);
        float gx = fmaf(g.x, 64.0f, 63.5f);   // (g+1)*64 - 0.5
        float gy = fmaf(g.y, 64.0f, 63.5f);

        float xf = floorf(gx);
        float yf = floorf(gy);
        float fx = gx - xf;      // 'w'
        float fy = gy - yf;      // 'n'
        float ex = 1.0f - fx;    // 'e'
        float sy = 1.0f - fy;    // 's'

        int x0 = (int)xf;
        int y0 = (int)yf;

        bool mx0 = (unsigned)x0 < 128u;
        bool mx1 = (unsigned)(x0 + 1) < 128u;
        bool my0 = (unsigned)y0 < 128u;
        bool my1 = (unsigned)(y0 + 1) < 128u;

        // base clamped so the whole 2x2 footprint is in-bounds
        int bx = min(max(x0, 0), 126);
        int by = min(max(y0, 0), 126);

        // x-axis weights mapped onto span [bx, bx+1]
        float ax_lo, ax_hi;
        if (mx0 & mx1)      { ax_lo = ex;   ax_hi = fx;   }
        else if (mx1)       { ax_lo = fx;   ax_hi = 0.0f; }
        else if (mx0)       { ax_lo = 0.0f; ax_hi = ex;   }
        else                { ax_lo = 0.0f; ax_hi = 0.0f; }

        float ay_lo, ay_hi;
        if (my0 & my1)      { ay_lo = sy;   ay_hi = fy;   }
        else if (my1)       { ay_lo = fy;   ay_hi = 0.0f; }
        else if (my0)       { ay_lo = 0.0f; ay_hi = sy;   }
        else                { ay_lo = 0.0f; ay_hi = 0.0f; }

        unsigned q00 = __float2uint_rn(ay_lo * ax_lo * 65535.0f);
        unsigned q01 = __float2uint_rn(ay_lo * ax_hi * 65535.0f);
        unsigned q10 = __float2uint_rn(ay_hi * ax_lo * 65535.0f);
        unsigned q11 = __float2uint_rn(ay_hi * ax_hi * 65535.0f);

        int4 prm;
        prm.x = ((by << 7) + bx) << 7;         // byte offset of (by,bx,c=0)
        prm.y = (int)(q00 | (q01 << 16));
        prm.z = (int)(q10 | (q11 << 16));
        prm.w = 0;
        s_p[t] = prm;
    }
    __syncthreads();

    // ---- Phase 2: 2 pixels per warp-iteration.
    //      lanes 0-15 -> pixel A (channels 2m,2m+1), lanes 16-31 -> pixel B.
    const int lane = t & 31;
    const int warp = t >> 5;
    const int half = lane >> 4;      // which pixel of the pair
    const int m    = lane & 15;      // channel pair index

    const char* __restrict__ srcB = (const char*)src + (m << 3);  // +8m bytes
    const int4* __restrict__ pp = s_p + (warp << 5) + half;        // stride 2 pixels
    char* __restrict__ outB = (char*)out
        + (((blockPix + (warp << 5) + half)) << 7) + (m << 3);

    #pragma unroll 4
    for (int it = 0; it < 16; ++it) {
        int4 prm = pp[it << 1];                 // LDS.128, imm offset

        const float2* a = (const float2*)(srcB + prm.x);
        float2 v00 = __ldg(a);                  // base + 0
        float2 v01 = __ldg(a + 16);             // base + 128 B   (x+1)
        float2 v10 = __ldg(a + 2048);           // base + 16384 B (y+1)
        float2 v11 = __ldg(a + 2064);           // base + 16512 B (y+1,x+1)

        unsigned pa = (unsigned)prm.y;
        unsigned pb = (unsigned)prm.z;
        float w00 = (float)(pa & 0xFFFFu);
        float w01 = (float)(pa >> 16);
        float w10 = (float)(pb & 0xFFFFu);
        float w11 = (float)(pb >> 16);

        float rx = fmaf(w00, v00.x, fmaf(w01, v01.x, fmaf(w10, v10.x, w11 * v11.x)));
        float ry = fmaf(w00, v00.y, fmaf(w01, v01.y, fmaf(w10, v10.y, w11 * v11.y)));

        float2 o2;
        o2.x = rx * (1.0f / 65535.0f);
        o2.y = ry * (1.0f / 65535.0f);
        *(float2*)(outB + (it << 8)) = o2;      // STG.64, imm offset (2 px = 256 B)
    }
}

extern "C" void kernel_launch(void* const* d_in, const int* in_sizes, int n_in,
                              void* d_out, int out_size)
{
    const float* src = (const float*)d_in[0];   // source (1,H,W,C)
    const float* mot = (const float*)d_in[1];   // motions (BS,NKP,H,W,2)
    float* out = (float*)d_out;

    deform_kernel<<<NBLOCKS_, 256>>>(src, mot, out);
}